// round 11
// baseline (speedup 1.0000x reference)
#include <cuda_runtime.h>

// Problem constants
#define BB 64
#define GG 1024
#define DD 256
#define LL 2
#define FF 1024
#define NEGV (-30.0f)

// ---------------------------------------------------------------------------
// Scratch (device globals — no allocation allowed in kernel_launch)
// ---------------------------------------------------------------------------
__device__ float g_q    [(size_t)BB * GG * DD];   // 64 MB
__device__ float g_k    [(size_t)BB * GG * DD];   // 64 MB
__device__ float g_v    [(size_t)BB * GG * DD];   // 64 MB
__device__ float g_heads[(size_t)BB * GG * DD];   // 64 MB
__device__ float g_h    [(size_t)BB * GG * DD];   // 64 MB
__device__ float g_c    [(size_t)BB * GG * GG];   // 256 MB (attention scores)
__device__ float g_t    [(size_t)BB * GG * FF];   // 256 MB (FFN hidden)

// ---------------------------------------------------------------------------
// Tiled SGEMM: C[b] = epilogue( alpha * A[b] @ op(B[b]) )
//   TRANS_B=false: B is [K,N] row-major (NN)
//   TRANS_B=true : B is [N,K] row-major (NT, i.e. A @ B^T)
// Epilogue: + bias[n] (if bias) + res[b][m,n] (if res), optional ReLU.
// Tile: BM=BN=128, BK=16, 256 threads, 8x8 microtile per thread.
// REQUIRES: M % 128 == 0, N % 128 == 0, K % 16 == 0 (true for all our shapes).
// ---------------------------------------------------------------------------
template <bool TRANS_B, bool RELU>
__global__ void __launch_bounds__(256, 2)
sgemm_kernel(const float* __restrict__ A, const float* __restrict__ Bm,
             const float* __restrict__ bias, const float* __restrict__ res,
             float* __restrict__ C,
             int M, int N, int K,
             long sA, long sB, long sC, long sRes,
             float alpha)
{
    const int tid = threadIdx.x;
    const int ty  = tid >> 4;   // 0..15  (M direction)
    const int tx  = tid & 15;   // 0..15  (N direction)

    const long bz = blockIdx.z;
    A  += bz * sA;
    Bm += bz * sB;
    C  += bz * sC;
    const float* resp = res ? (res + bz * sRes) : (const float*)0;

    const int m0 = blockIdx.y * 128;
    const int n0 = blockIdx.x * 128;

    __shared__ float As[16][128];
    __shared__ float Bs[16][128];

    float acc[8][8];
#pragma unroll
    for (int i = 0; i < 8; i++)
#pragma unroll
        for (int j = 0; j < 8; j++) acc[i][j] = 0.0f;

    for (int k0 = 0; k0 < K; k0 += 16) {
        // ---- load A tile (transposed into As[k][m]) ----
#pragma unroll
        for (int it = 0; it < 2; it++) {
            int lin = tid + it * 256;        // 0..511
            int row = lin >> 2;              // 0..127
            int kc  = (lin & 3) * 4;         // 0,4,8,12
            float4 va = *(const float4*)(A + (long)(m0 + row) * K + k0 + kc);
            As[kc + 0][row] = va.x;
            As[kc + 1][row] = va.y;
            As[kc + 2][row] = va.z;
            As[kc + 3][row] = va.w;
        }
        // ---- load B tile into Bs[k][n] ----
        if (TRANS_B) {
#pragma unroll
            for (int it = 0; it < 2; it++) {
                int lin = tid + it * 256;
                int n   = lin >> 2;          // 0..127
                int kc  = (lin & 3) * 4;
                float4 vb = *(const float4*)(Bm + (long)(n0 + n) * K + k0 + kc);
                Bs[kc + 0][n] = vb.x;
                Bs[kc + 1][n] = vb.y;
                Bs[kc + 2][n] = vb.z;
                Bs[kc + 3][n] = vb.w;
            }
        } else {
#pragma unroll
            for (int it = 0; it < 2; it++) {
                int lin = tid + it * 256;
                int kk  = lin >> 5;          // 0..15
                int nc  = (lin & 31) * 4;    // 0..124
                float4 vb = *(const float4*)(Bm + (long)(k0 + kk) * N + n0 + nc);
                *(float4*)&Bs[kk][nc] = vb;
            }
        }
        __syncthreads();

        // ---- 128x128x16 FMA block ----
#pragma unroll
        for (int k = 0; k < 16; k++) {
            float a[8], b[8];
            *(float4*)&a[0] = *(const float4*)&As[k][ty * 8];
            *(float4*)&a[4] = *(const float4*)&As[k][ty * 8 + 4];
            *(float4*)&b[0] = *(const float4*)&Bs[k][tx * 8];
            *(float4*)&b[4] = *(const float4*)&Bs[k][tx * 8 + 4];
#pragma unroll
            for (int i = 0; i < 8; i++)
#pragma unroll
                for (int j = 0; j < 8; j++)
                    acc[i][j] += a[i] * b[j];
        }
        __syncthreads();
    }

    // ---- epilogue ----
#pragma unroll
    for (int i = 0; i < 8; i++) {
        int m = m0 + ty * 8 + i;
#pragma unroll
        for (int j = 0; j < 8; j += 4) {
            int n = n0 + tx * 8 + j;
            float4 v;
            v.x = acc[i][j + 0] * alpha;
            v.y = acc[i][j + 1] * alpha;
            v.z = acc[i][j + 2] * alpha;
            v.w = acc[i][j + 3] * alpha;
            if (bias) {
                v.x += bias[n + 0];
                v.y += bias[n + 1];
                v.z += bias[n + 2];
                v.w += bias[n + 3];
            }
            if (resp) {
                float4 r = *(const float4*)(resp + (long)m * N + n);
                v.x += r.x; v.y += r.y; v.z += r.z; v.w += r.w;
            }
            if (RELU) {
                v.x = fmaxf(v.x, 0.0f);
                v.y = fmaxf(v.y, 0.0f);
                v.z = fmaxf(v.z, 0.0f);
                v.w = fmaxf(v.w, 0.0f);
            }
            *(float4*)(C + (long)m * N + n) = v;
        }
    }
}

// ---------------------------------------------------------------------------
// Masked softmax over the last dim of c[B,G,G] (in place).
// Matches reference exactly: masked -> -30 before softmax (still contributes
// exp(-30-max) to the denominator), masked -> 0 after softmax.
// One block per (q, b) row; 256 threads x 4 elements.
// ---------------------------------------------------------------------------
__global__ void __launch_bounds__(256)
softmax_mask_kernel(float* __restrict__ c, const int* __restrict__ mask)
{
    const int q = blockIdx.x;
    const int b = blockIdx.y;
    float* row = c + ((long)b * GG + q) * GG;
    const int* mrow = mask + b * GG;
    const int tid = threadIdx.x;

    float vals[4];
    int   msk[4];
    float mx = -1e30f;
#pragma unroll
    for (int t = 0; t < 4; t++) {
        int idx = tid + t * 256;
        int m = mrow[idx];
        float v = m ? NEGV : row[idx];
        vals[t] = v;
        msk[t]  = m;
        mx = fmaxf(mx, v);
    }

    __shared__ float red[8];
    // warp max
#pragma unroll
    for (int o = 16; o; o >>= 1) mx = fmaxf(mx, __shfl_xor_sync(0xffffffffu, mx, o));
    if ((tid & 31) == 0) red[tid >> 5] = mx;
    __syncthreads();
    {
        float v = red[tid & 7];
        mx = fmaxf(fmaxf(fmaxf(red[0], red[1]), fmaxf(red[2], red[3])),
                   fmaxf(fmaxf(red[4], red[5]), fmaxf(red[6], red[7])));
        (void)v;
    }
    __syncthreads();

    float e[4];
    float s = 0.0f;
#pragma unroll
    for (int t = 0; t < 4; t++) {
        e[t] = __expf(vals[t] - mx);
        s += e[t];
    }
    // warp sum
#pragma unroll
    for (int o = 16; o; o >>= 1) s += __shfl_xor_sync(0xffffffffu, s, o);
    if ((tid & 31) == 0) red[tid >> 5] = s;
    __syncthreads();
    float tot = red[0] + red[1] + red[2] + red[3]
              + red[4] + red[5] + red[6] + red[7];
    float inv = 1.0f / tot;

#pragma unroll
    for (int t = 0; t < 4; t++) {
        int idx = tid + t * 256;
        row[idx] = msk[t] ? 0.0f : e[t] * inv;
    }
}

// ---------------------------------------------------------------------------
// mean over G: mean[b,d] = (1/G) * sum_g h[b,g,d]. One block per batch,
// one thread per d (coalesced across threads). Deterministic (no atomics).
// ---------------------------------------------------------------------------
__global__ void __launch_bounds__(DD)
mean_kernel(const float* __restrict__ h, float* __restrict__ mean)
{
    const int b = blockIdx.x;
    const int d = threadIdx.x;
    const float* p = h + (long)b * GG * DD + d;
    float s = 0.0f;
#pragma unroll 8
    for (int g = 0; g < GG; g++)
        s += p[(long)g * DD];
    mean[b * DD + d] = s * (1.0f / (float)GG);
}

// ---------------------------------------------------------------------------
// Host launcher
// ---------------------------------------------------------------------------
extern "C" void kernel_launch(void* const* d_in, const int* in_sizes, int n_in,
                              void* d_out, int out_size)
{
    (void)in_sizes; (void)n_in; (void)out_size;

    const float* x    = (const float*)d_in[0];
    const int*   mask = (const int*)  d_in[1];
    const float* Wq   = (const float*)d_in[2];
    const float* Wk   = (const float*)d_in[3];
    const float* Wv   = (const float*)d_in[4];
    const float* Wo   = (const float*)d_in[5];
    const float* bo   = (const float*)d_in[6];
    const float* Wf1  = (const float*)d_in[7];
    const float* bf1  = (const float*)d_in[8];
    const float* Wf2  = (const float*)d_in[9];
    const float* bf2  = (const float*)d_in[10];
    float* out = (float*)d_out;

    float *q, *k, *v, *heads, *h, *c, *t;
    cudaGetSymbolAddress((void**)&q,     g_q);
    cudaGetSymbolAddress((void**)&k,     g_k);
    cudaGetSymbolAddress((void**)&v,     g_v);
    cudaGetSymbolAddress((void**)&heads, g_heads);
    cudaGetSymbolAddress((void**)&h,     g_h);
    cudaGetSymbolAddress((void**)&c,     g_c);
    cudaGetSymbolAddress((void**)&t,     g_t);

    const int  BG     = BB * GG;                 // 65536
    const long strQKV = (long)GG * DD;           // per-batch stride for q/k/v
    const long strC   = (long)GG * GG;           // per-batch stride for scores
    const dim3 blk(256);

    const dim3 gProj(DD / 128, BG / 128, 1);     // (2, 512)
    const dim3 gScores(GG / 128, GG / 128, BB);  // (8, 8, 64)
    const dim3 gHeads(DD / 128, GG / 128, BB);   // (2, 8, 64)
    const dim3 gFfn1(FF / 128, BG / 128, 1);     // (8, 512)

    const float* hin = x;
    for (int l = 0; l < LL; l++) {
        const float* wq = Wq  + (long)l * DD * DD;
        const float* wk = Wk  + (long)l * DD * DD;
        const float* wv = Wv  + (long)l * DD * DD;
        const float* wo = Wo  + (long)l * DD * DD;
        const float* w1 = Wf1 + (long)l * DD * FF;
        const float* w2 = Wf2 + (long)l * FF * DD;
        const float* b_o = bo  + l * DD;
        const float* b_1 = bf1 + l * FF;
        const float* b_2 = bf2 + l * DD;

        // Q, K, V projections: [BG,D] @ [D,D]
        sgemm_kernel<false, false><<<gProj, blk>>>(hin, wq, 0, 0, q,
            BG, DD, DD, 0, 0, 0, 0, 1.0f);
        sgemm_kernel<false, false><<<gProj, blk>>>(hin, wk, 0, 0, k,
            BG, DD, DD, 0, 0, 0, 0, 1.0f);
        sgemm_kernel<false, false><<<gProj, blk>>>(hin, wv, 0, 0, v,
            BG, DD, DD, 0, 0, 0, 0, 1.0f);

        // scores: c[b] = (1/16) * q[b] @ k[b]^T   (batched NT)
        sgemm_kernel<true, false><<<gScores, blk>>>(q, k, 0, 0, c,
            GG, GG, DD, strQKV, strQKV, strC, 0, 0.0625f);

        // masked softmax (in place on c)
        softmax_mask_kernel<<<dim3(GG, BB), 256>>>(c, mask);

        // heads: heads[b] = a[b] @ v[b]   (batched NN)
        sgemm_kernel<false, false><<<gHeads, blk>>>(c, v, 0, 0, heads,
            GG, DD, GG, strC, strQKV, strQKV, 0, 1.0f);

        // output projection + residual: h = hin + heads @ Wo + bo
        sgemm_kernel<false, false><<<gProj, blk>>>(heads, wo, b_o, hin, h,
            BG, DD, DD, 0, 0, 0, 0, 1.0f);

        // FFN up + ReLU: t = relu(h @ Wf1 + bf1)
        sgemm_kernel<false, true><<<gFfn1, blk>>>(h, w1, b_1, 0, t,
            BG, FF, DD, 0, 0, 0, 0, 1.0f);

        // FFN down + residual: h = h + t @ Wf2 + bf2
        float* hout = (l == LL - 1) ? out : h;
        sgemm_kernel<false, false><<<gProj, blk>>>(t, w2, b_2, h, hout,
            BG, DD, FF, 0, 0, 0, 0, 1.0f);

        hin = h;
    }

    // mean over the graph dim, appended after h in the output buffer
    mean_kernel<<<BB, DD>>>(out, out + (long)BB * GG * DD);
}

// round 15
// speedup vs baseline: 2.5330x; 2.5330x over previous
#include <cuda_runtime.h>
#include <cstdint>

// Problem constants
#define BB 64
#define GG 1024
#define DD 256
#define LL 2
#define FF 1024
#define NEGV (-30.0f)

// ---------------------------------------------------------------------------
// Scratch (device globals — no allocation allowed in kernel_launch)
// ---------------------------------------------------------------------------
__device__ float g_q    [(size_t)BB * GG * DD];
__device__ float g_k    [(size_t)BB * GG * DD];
__device__ float g_v    [(size_t)BB * GG * DD];
__device__ float g_heads[(size_t)BB * GG * DD];
__device__ float g_h    [(size_t)BB * GG * DD];
__device__ float g_c    [(size_t)BB * GG * GG];
__device__ float g_t    [(size_t)BB * GG * FF];

// ---------------------------------------------------------------------------
// Helpers
// ---------------------------------------------------------------------------
__device__ __forceinline__ uint32_t f2tf32(float x) {
    uint32_t u;
    asm("cvt.rna.tf32.f32 %0, %1;" : "=r"(u) : "f"(x));
    return u;
}

__device__ __forceinline__ void mma8(float& c0, float& c1, float& c2, float& c3,
                                     uint32_t a0, uint32_t a1, uint32_t a2, uint32_t a3,
                                     uint32_t b0, uint32_t b1) {
    asm volatile(
        "mma.sync.aligned.m16n8k8.row.col.f32.tf32.tf32.f32 "
        "{%0,%1,%2,%3}, {%4,%5,%6,%7}, {%8,%9}, {%0,%1,%2,%3};"
        : "+f"(c0), "+f"(c1), "+f"(c2), "+f"(c3)
        : "r"(a0), "r"(a1), "r"(a2), "r"(a3), "r"(b0), "r"(b1));
}

// ---------------------------------------------------------------------------
// tf32 tensor-core GEMM via mma.sync (compute_103-compatible).
//   C[b] = epi( alpha * A[b] @ op(B[b]) )
//   TRANS_B=false: B is [K,N] row-major (NN)
//   TRANS_B=true : B is [N,K] row-major (NT, i.e. A @ B^T)
// CTA tile 128x128, BK=16, 256 threads (8 warps, warp tile 64x32).
// Requires M%128==0, N%128==0, K%16==0 (true for all shapes here).
//
// SMEM:
//   As: [128][APITCH=20]  (m-major; frag loads conflict-free: banks 20g+tig)
//   Bs: [16][BPITCH=132]  (k-major; frag loads conflict-free: banks 4tig+g)
//   stage (epilogue, reuses As/Bs): [32][132]
// ---------------------------------------------------------------------------
#define APITCH 20
#define BPITCH 132
#define SPITCH 132
#define AS_WORDS (128 * APITCH)                 /* 2560 */
#define SMEM_WORDS (AS_WORDS + 16 * BPITCH)     /* 4672 */
#define SMEM_BYTES (SMEM_WORDS * 4)             /* 18688 */

template <bool TRANS_B, bool RELU>
__global__ void __launch_bounds__(256, 2)
mma_gemm(const float* __restrict__ A, const float* __restrict__ B,
         const float* __restrict__ bias, const float* __restrict__ res,
         float* __restrict__ C,
         int M, int N, int K,
         long sA, long sB, long sC, long sRes,
         float alpha)
{
    extern __shared__ float sm[];
    float* As    = sm;              // [128][20]
    float* Bs    = sm + AS_WORDS;   // [16][132]
    float* stage = sm;              // epilogue reuse [32][132]

    const int tid  = threadIdx.x;
    const int lane = tid & 31;
    const int wid  = tid >> 5;
    const int gq   = lane >> 2;     // 0..7 (group id)
    const int tg   = lane & 3;      // 0..3 (thread-in-group)
    const int wm   = wid & 1;       // warp m index (2)
    const int wn   = wid >> 1;      // warp n index (4)

    const long bz = blockIdx.z;
    const int  m0 = blockIdx.y * 128;
    const int  n0 = blockIdx.x * 128;

    const float* Ab = A + bz * sA + (long)m0 * K;
    const float* Bb = TRANS_B ? (B + bz * sB + (long)n0 * K)
                              : (B + bz * sB + n0);

    float acc[4][4][4];
#pragma unroll
    for (int i = 0; i < 4; i++)
#pragma unroll
        for (int j = 0; j < 4; j++)
#pragma unroll
            for (int p = 0; p < 4; p++) acc[i][j][p] = 0.0f;

    const int NC = K >> 4;          // chunks of 16

    float4 ra[2], rb[2];
    // prefetch chunk 0
#pragma unroll
    for (int i = 0; i < 2; i++) {
        int lin = tid + i * 256;
        int r = lin >> 2, q = lin & 3;
        ra[i] = *(const float4*)(Ab + (long)r * K + 4 * q);
        if (TRANS_B) {
            rb[i] = *(const float4*)(Bb + (long)r * K + 4 * q);
        } else {
            int kk = lin >> 5, nq = lin & 31;
            rb[i] = *(const float4*)(Bb + (long)kk * N + 4 * nq);
        }
    }

    for (int c = 0; c < NC; c++) {
        // ---- stage current chunk into SMEM (convert to tf32) ----
#pragma unroll
        for (int i = 0; i < 2; i++) {
            int lin = tid + i * 256;
            int r = lin >> 2, q = lin & 3;
            uint4 u;
            u.x = f2tf32(ra[i].x); u.y = f2tf32(ra[i].y);
            u.z = f2tf32(ra[i].z); u.w = f2tf32(ra[i].w);
            *(uint4*)(As + r * APITCH + 4 * q) = u;
            if (TRANS_B) {
                // scatter: B[n0+r][k0+4q..] -> Bs[k][n=r]
                uint4 v;
                v.x = f2tf32(rb[i].x); v.y = f2tf32(rb[i].y);
                v.z = f2tf32(rb[i].z); v.w = f2tf32(rb[i].w);
                Bs[(4 * q + 0) * BPITCH + r] = __uint_as_float(v.x);
                Bs[(4 * q + 1) * BPITCH + r] = __uint_as_float(v.y);
                Bs[(4 * q + 2) * BPITCH + r] = __uint_as_float(v.z);
                Bs[(4 * q + 3) * BPITCH + r] = __uint_as_float(v.w);
            } else {
                int kk = lin >> 5, nq = lin & 31;
                uint4 v;
                v.x = f2tf32(rb[i].x); v.y = f2tf32(rb[i].y);
                v.z = f2tf32(rb[i].z); v.w = f2tf32(rb[i].w);
                *(uint4*)(Bs + kk * BPITCH + 4 * nq) = v;
            }
        }
        __syncthreads();

        // ---- prefetch next chunk (overlaps with MMA below) ----
        if (c + 1 < NC) {
            const float* Ac = Ab + (c + 1) * 16;
#pragma unroll
            for (int i = 0; i < 2; i++) {
                int lin = tid + i * 256;
                int r = lin >> 2, q = lin & 3;
                ra[i] = *(const float4*)(Ac + (long)r * K + 4 * q);
                if (TRANS_B) {
                    const float* Bc = Bb + (c + 1) * 16;
                    rb[i] = *(const float4*)(Bc + (long)r * K + 4 * q);
                } else {
                    int kk = lin >> 5, nq = lin & 31;
                    const float* Bc = Bb + (long)((c + 1) * 16) * N;
                    rb[i] = *(const float4*)(Bc + (long)kk * N + 4 * nq);
                }
            }
        }

        // ---- compute: 2 k-steps of 8 ----
#pragma unroll
        for (int ks = 0; ks < 16; ks += 8) {
            uint32_t bf[4][2], af[4][4];
#pragma unroll
            for (int nt = 0; nt < 4; nt++) {
                int nn = wn * 32 + nt * 8 + gq;
                bf[nt][0] = __float_as_uint(Bs[(ks + tg)     * BPITCH + nn]);
                bf[nt][1] = __float_as_uint(Bs[(ks + tg + 4) * BPITCH + nn]);
            }
#pragma unroll
            for (int mt = 0; mt < 4; mt++) {
                int mm = wm * 64 + mt * 16;
                af[mt][0] = __float_as_uint(As[(mm + gq)     * APITCH + ks + tg]);
                af[mt][1] = __float_as_uint(As[(mm + gq + 8) * APITCH + ks + tg]);
                af[mt][2] = __float_as_uint(As[(mm + gq)     * APITCH + ks + tg + 4]);
                af[mt][3] = __float_as_uint(As[(mm + gq + 8) * APITCH + ks + tg + 4]);
            }
#pragma unroll
            for (int mt = 0; mt < 4; mt++)
#pragma unroll
                for (int nt = 0; nt < 4; nt++)
                    mma8(acc[mt][nt][0], acc[mt][nt][1], acc[mt][nt][2], acc[mt][nt][3],
                         af[mt][0], af[mt][1], af[mt][2], af[mt][3],
                         bf[nt][0], bf[nt][1]);
        }
        __syncthreads();
    }

    // ---- epilogue: stage through SMEM for coalesced float4 writes ----
    const float* resb = res ? (res + bz * sRes) : (const float*)0;
    float* Cb = C + bz * sC;

#pragma unroll
    for (int mt = 0; mt < 4; mt++) {
        // store fragments (STS.64, conflict-free: banks 4g+8nt+2tg distinct)
#pragma unroll
        for (int nt = 0; nt < 4; nt++) {
            int col = wn * 32 + nt * 8 + tg * 2;
            int rl  = wm * 16 + gq;
            float2 lo = make_float2(acc[mt][nt][0], acc[mt][nt][1]);
            float2 hi = make_float2(acc[mt][nt][2], acc[mt][nt][3]);
            *(float2*)(stage + rl * SPITCH + col)       = lo;
            *(float2*)(stage + (rl + 8) * SPITCH + col) = hi;
        }
        __syncthreads();

        // 32 rows x 128 cols -> global, fused epilogue
#pragma unroll
        for (int it = 0; it < 4; it++) {
            int lin = tid + it * 256;
            int rl = lin >> 5, q = lin & 31;
            float4 v = *(float4*)(stage + rl * SPITCH + 4 * q);
            int mrow = (rl < 16) ? (mt * 16 + rl) : (64 + mt * 16 + (rl - 16));
            int m = m0 + mrow;
            int n = n0 + 4 * q;
            v.x *= alpha; v.y *= alpha; v.z *= alpha; v.w *= alpha;
            if (bias) {
                float4 bv = *(const float4*)(bias + n);
                v.x += bv.x; v.y += bv.y; v.z += bv.z; v.w += bv.w;
            }
            if (resb) {
                float4 rv = *(const float4*)(resb + (long)m * N + n);
                v.x += rv.x; v.y += rv.y; v.z += rv.z; v.w += rv.w;
            }
            if (RELU) {
                v.x = fmaxf(v.x, 0.0f); v.y = fmaxf(v.y, 0.0f);
                v.z = fmaxf(v.z, 0.0f); v.w = fmaxf(v.w, 0.0f);
            }
            *(float4*)(Cb + (long)m * N + n) = v;
        }
        __syncthreads();
    }
}

// ---------------------------------------------------------------------------
// Masked softmax over the last dim of c[B,G,G] (in place). Matches reference:
// masked -> -30 pre-softmax (contributes to denominator), masked -> 0 post.
// ---------------------------------------------------------------------------
__global__ void __launch_bounds__(256)
softmax_mask_kernel(float* __restrict__ c, const int* __restrict__ mask)
{
    const int q = blockIdx.x;
    const int b = blockIdx.y;
    float* row = c + ((long)b * GG + q) * GG;
    const int* mrow = mask + b * GG;
    const int tid = threadIdx.x;

    float vals[4];
    int   msk[4];
    float mx = -1e30f;
#pragma unroll
    for (int t = 0; t < 4; t++) {
        int idx = tid + t * 256;
        int m = mrow[idx];
        float v = m ? NEGV : row[idx];
        vals[t] = v;
        msk[t]  = m;
        mx = fmaxf(mx, v);
    }

    __shared__ float red[8];
#pragma unroll
    for (int o = 16; o; o >>= 1) mx = fmaxf(mx, __shfl_xor_sync(0xffffffffu, mx, o));
    if ((tid & 31) == 0) red[tid >> 5] = mx;
    __syncthreads();
    mx = fmaxf(fmaxf(fmaxf(red[0], red[1]), fmaxf(red[2], red[3])),
               fmaxf(fmaxf(red[4], red[5]), fmaxf(red[6], red[7])));
    __syncthreads();

    float e[4];
    float s = 0.0f;
#pragma unroll
    for (int t = 0; t < 4; t++) {
        e[t] = __expf(vals[t] - mx);
        s += e[t];
    }
#pragma unroll
    for (int o = 16; o; o >>= 1) s += __shfl_xor_sync(0xffffffffu, s, o);
    if ((tid & 31) == 0) red[tid >> 5] = s;
    __syncthreads();
    float tot = red[0] + red[1] + red[2] + red[3]
              + red[4] + red[5] + red[6] + red[7];
    float inv = 1.0f / tot;

#pragma unroll
    for (int t = 0; t < 4; t++) {
        int idx = tid + t * 256;
        row[idx] = msk[t] ? 0.0f : e[t] * inv;
    }
}

// ---------------------------------------------------------------------------
// mean over G (deterministic, no atomics)
// ---------------------------------------------------------------------------
__global__ void __launch_bounds__(DD)
mean_kernel(const float* __restrict__ h, float* __restrict__ mean)
{
    const int b = blockIdx.x;
    const int d = threadIdx.x;
    const float* p = h + (long)b * GG * DD + d;
    float s = 0.0f;
#pragma unroll 8
    for (int g = 0; g < GG; g++)
        s += p[(long)g * DD];
    mean[b * DD + d] = s * (1.0f / (float)GG);
}

// ---------------------------------------------------------------------------
// Host launcher
// ---------------------------------------------------------------------------
extern "C" void kernel_launch(void* const* d_in, const int* in_sizes, int n_in,
                              void* d_out, int out_size)
{
    (void)in_sizes; (void)n_in; (void)out_size;

    const float* x    = (const float*)d_in[0];
    const int*   mask = (const int*)  d_in[1];
    const float* Wq   = (const float*)d_in[2];
    const float* Wk   = (const float*)d_in[3];
    const float* Wv   = (const float*)d_in[4];
    const float* Wo   = (const float*)d_in[5];
    const float* bo   = (const float*)d_in[6];
    const float* Wf1  = (const float*)d_in[7];
    const float* bf1  = (const float*)d_in[8];
    const float* Wf2  = (const float*)d_in[9];
    const float* bf2  = (const float*)d_in[10];
    float* out = (float*)d_out;

    float *q, *k, *v, *heads, *h, *c, *t;
    cudaGetSymbolAddress((void**)&q,     g_q);
    cudaGetSymbolAddress((void**)&k,     g_k);
    cudaGetSymbolAddress((void**)&v,     g_v);
    cudaGetSymbolAddress((void**)&heads, g_heads);
    cudaGetSymbolAddress((void**)&h,     g_h);
    cudaGetSymbolAddress((void**)&c,     g_c);
    cudaGetSymbolAddress((void**)&t,     g_t);

    const int  BG     = BB * GG;                 // 65536
    const long strQKV = (long)GG * DD;
    const long strC   = (long)GG * GG;
    const dim3 blk(256);

    const dim3 gProj(DD / 128, BG / 128, 1);     // (2, 512)
    const dim3 gScores(GG / 128, GG / 128, BB);  // (8, 8, 64)
    const dim3 gHeads(DD / 128, GG / 128, BB);   // (2, 8, 64)
    const dim3 gFfn1(FF / 128, BG / 128, 1);     // (8, 512)

    const float* hin = x;
    for (int l = 0; l < LL; l++) {
        const float* wq = Wq  + (long)l * DD * DD;
        const float* wk = Wk  + (long)l * DD * DD;
        const float* wv = Wv  + (long)l * DD * DD;
        const float* wo = Wo  + (long)l * DD * DD;
        const float* w1 = Wf1 + (long)l * DD * FF;
        const float* w2 = Wf2 + (long)l * FF * DD;
        const float* b_o = bo  + l * DD;
        const float* b_1 = bf1 + l * FF;
        const float* b_2 = bf2 + l * DD;

        // Q, K, V projections: [BG,D] @ [D,D]  (NN)
        mma_gemm<false, false><<<gProj, blk, SMEM_BYTES>>>(hin, wq, 0, 0, q,
            BG, DD, DD, 0, 0, 0, 0, 1.0f);
        mma_gemm<false, false><<<gProj, blk, SMEM_BYTES>>>(hin, wk, 0, 0, k,
            BG, DD, DD, 0, 0, 0, 0, 1.0f);
        mma_gemm<false, false><<<gProj, blk, SMEM_BYTES>>>(hin, wv, 0, 0, v,
            BG, DD, DD, 0, 0, 0, 0, 1.0f);

        // scores: c[b] = (1/16) * q[b] @ k[b]^T  (NT)
        mma_gemm<true, false><<<gScores, blk, SMEM_BYTES>>>(q, k, 0, 0, c,
            GG, GG, DD, strQKV, strQKV, strC, 0, 0.0625f);

        softmax_mask_kernel<<<dim3(GG, BB), 256>>>(c, mask);

        // heads[b] = a[b] @ v[b]  (NN)
        mma_gemm<false, false><<<gHeads, blk, SMEM_BYTES>>>(c, v, 0, 0, heads,
            GG, DD, GG, strC, strQKV, strQKV, 0, 1.0f);

        // h = hin + heads @ Wo + bo  (NN)
        mma_gemm<false, false><<<gProj, blk, SMEM_BYTES>>>(heads, wo, b_o, hin, h,
            BG, DD, DD, 0, 0, 0, 0, 1.0f);

        // t = relu(h @ Wf1 + bf1)  (NN)
        mma_gemm<false, true><<<gFfn1, blk, SMEM_BYTES>>>(h, w1, b_1, 0, t,
            BG, FF, DD, 0, 0, 0, 0, 1.0f);

        // hout = h + t @ Wf2 + bf2  (NN)
        float* hout = (l == LL - 1) ? out : h;
        mma_gemm<false, false><<<gProj, blk, SMEM_BYTES>>>(t, w2, b_2, h, hout,
            BG, DD, FF, 0, 0, 0, 0, 1.0f);

        hin = h;
    }

    mean_kernel<<<BB, DD>>>(out, out + (long)BB * GG * DD);
}

// round 16
// speedup vs baseline: 2.5332x; 1.0001x over previous
#include <cuda_runtime.h>
#include <cstdint>

// Problem constants
#define BB 64
#define GG 1024
#define DD 256
#define LL 2
#define FF 1024
#define NEGV (-30.0f)

// ---------------------------------------------------------------------------
// Scratch (device globals — no allocation allowed in kernel_launch)
// ---------------------------------------------------------------------------
__device__ float g_q    [(size_t)BB * GG * DD];
__device__ float g_k    [(size_t)BB * GG * DD];
__device__ float g_v    [(size_t)BB * GG * DD];
__device__ float g_heads[(size_t)BB * GG * DD];
__device__ float g_h    [(size_t)BB * GG * DD];
__device__ float g_c    [(size_t)BB * GG * GG];
__device__ float g_t    [(size_t)BB * GG * FF];

// ---------------------------------------------------------------------------
// Helpers
// ---------------------------------------------------------------------------
__device__ __forceinline__ uint32_t f2tf32(float x) {
    uint32_t u;
    asm("cvt.rna.tf32.f32 %0, %1;" : "=r"(u) : "f"(x));
    return u;
}

__device__ __forceinline__ void mma8(float& c0, float& c1, float& c2, float& c3,
                                     uint32_t a0, uint32_t a1, uint32_t a2, uint32_t a3,
                                     uint32_t b0, uint32_t b1) {
    asm volatile(
        "mma.sync.aligned.m16n8k8.row.col.f32.tf32.tf32.f32 "
        "{%0,%1,%2,%3}, {%4,%5,%6,%7}, {%8,%9}, {%0,%1,%2,%3};"
        : "+f"(c0), "+f"(c1), "+f"(c2), "+f"(c3)
        : "r"(a0), "r"(a1), "r"(a2), "r"(a3), "r"(b0), "r"(b1));
}

// ---------------------------------------------------------------------------
// tf32 tensor-core GEMM via mma.sync (compute_103-compatible).
//   C[b] = epi( alpha * A[b] @ op(B[b]) )
//   TRANS_B=false: B is [K,N] row-major (NN)
//   TRANS_B=true : B is [N,K] row-major (NT, i.e. A @ B^T)
// CTA tile 128x128, BK=16, 256 threads (8 warps, warp tile 64x32).
// Requires M%128==0, N%128==0, K%16==0 (true for all shapes here).
//
// SMEM:
//   As: [128][APITCH=20]  (m-major; frag loads conflict-free: banks 20g+tig)
//   Bs: [16][BPITCH=132]  (k-major; frag loads conflict-free: banks 4tig+g)
//   stage (epilogue, reuses As/Bs): [32][132]
// ---------------------------------------------------------------------------
#define APITCH 20
#define BPITCH 132
#define SPITCH 132
#define AS_WORDS (128 * APITCH)                 /* 2560 */
#define SMEM_WORDS (AS_WORDS + 16 * BPITCH)     /* 4672 */
#define SMEM_BYTES (SMEM_WORDS * 4)             /* 18688 */

template <bool TRANS_B, bool RELU>
__global__ void __launch_bounds__(256, 2)
mma_gemm(const float* __restrict__ A, const float* __restrict__ B,
         const float* __restrict__ bias, const float* __restrict__ res,
         float* __restrict__ C,
         int M, int N, int K,
         long sA, long sB, long sC, long sRes,
         float alpha)
{
    extern __shared__ float sm[];
    float* As    = sm;              // [128][20]
    float* Bs    = sm + AS_WORDS;   // [16][132]
    float* stage = sm;              // epilogue reuse [32][132]

    const int tid  = threadIdx.x;
    const int lane = tid & 31;
    const int wid  = tid >> 5;
    const int gq   = lane >> 2;     // 0..7 (group id)
    const int tg   = lane & 3;      // 0..3 (thread-in-group)
    const int wm   = wid & 1;       // warp m index (2)
    const int wn   = wid >> 1;      // warp n index (4)

    const long bz = blockIdx.z;
    const int  m0 = blockIdx.y * 128;
    const int  n0 = blockIdx.x * 128;

    const float* Ab = A + bz * sA + (long)m0 * K;
    const float* Bb = TRANS_B ? (B + bz * sB + (long)n0 * K)
                              : (B + bz * sB + n0);

    float acc[4][4][4];
#pragma unroll
    for (int i = 0; i < 4; i++)
#pragma unroll
        for (int j = 0; j < 4; j++)
#pragma unroll
            for (int p = 0; p < 4; p++) acc[i][j][p] = 0.0f;

    const int NC = K >> 4;          // chunks of 16

    float4 ra[2], rb[2];
    // prefetch chunk 0
#pragma unroll
    for (int i = 0; i < 2; i++) {
        int lin = tid + i * 256;
        int r = lin >> 2, q = lin & 3;
        ra[i] = *(const float4*)(Ab + (long)r * K + 4 * q);
        if (TRANS_B) {
            rb[i] = *(const float4*)(Bb + (long)r * K + 4 * q);
        } else {
            int kk = lin >> 5, nq = lin & 31;
            rb[i] = *(const float4*)(Bb + (long)kk * N + 4 * nq);
        }
    }

    for (int c = 0; c < NC; c++) {
        // ---- stage current chunk into SMEM (convert to tf32) ----
#pragma unroll
        for (int i = 0; i < 2; i++) {
            int lin = tid + i * 256;
            int r = lin >> 2, q = lin & 3;
            uint4 u;
            u.x = f2tf32(ra[i].x); u.y = f2tf32(ra[i].y);
            u.z = f2tf32(ra[i].z); u.w = f2tf32(ra[i].w);
            *(uint4*)(As + r * APITCH + 4 * q) = u;
            if (TRANS_B) {
                // scatter: B[n0+r][k0+4q..] -> Bs[k][n=r]
                uint4 v;
                v.x = f2tf32(rb[i].x); v.y = f2tf32(rb[i].y);
                v.z = f2tf32(rb[i].z); v.w = f2tf32(rb[i].w);
                Bs[(4 * q + 0) * BPITCH + r] = __uint_as_float(v.x);
                Bs[(4 * q + 1) * BPITCH + r] = __uint_as_float(v.y);
                Bs[(4 * q + 2) * BPITCH + r] = __uint_as_float(v.z);
                Bs[(4 * q + 3) * BPITCH + r] = __uint_as_float(v.w);
            } else {
                int kk = lin >> 5, nq = lin & 31;
                uint4 v;
                v.x = f2tf32(rb[i].x); v.y = f2tf32(rb[i].y);
                v.z = f2tf32(rb[i].z); v.w = f2tf32(rb[i].w);
                *(uint4*)(Bs + kk * BPITCH + 4 * nq) = v;
            }
        }
        __syncthreads();

        // ---- prefetch next chunk (overlaps with MMA below) ----
        if (c + 1 < NC) {
            const float* Ac = Ab + (c + 1) * 16;
#pragma unroll
            for (int i = 0; i < 2; i++) {
                int lin = tid + i * 256;
                int r = lin >> 2, q = lin & 3;
                ra[i] = *(const float4*)(Ac + (long)r * K + 4 * q);
                if (TRANS_B) {
                    const float* Bc = Bb + (c + 1) * 16;
                    rb[i] = *(const float4*)(Bc + (long)r * K + 4 * q);
                } else {
                    int kk = lin >> 5, nq = lin & 31;
                    const float* Bc = Bb + (long)((c + 1) * 16) * N;
                    rb[i] = *(const float4*)(Bc + (long)kk * N + 4 * nq);
                }
            }
        }

        // ---- compute: 2 k-steps of 8 ----
#pragma unroll
        for (int ks = 0; ks < 16; ks += 8) {
            uint32_t bf[4][2], af[4][4];
#pragma unroll
            for (int nt = 0; nt < 4; nt++) {
                int nn = wn * 32 + nt * 8 + gq;
                bf[nt][0] = __float_as_uint(Bs[(ks + tg)     * BPITCH + nn]);
                bf[nt][1] = __float_as_uint(Bs[(ks + tg + 4) * BPITCH + nn]);
            }
#pragma unroll
            for (int mt = 0; mt < 4; mt++) {
                int mm = wm * 64 + mt * 16;
                af[mt][0] = __float_as_uint(As[(mm + gq)     * APITCH + ks + tg]);
                af[mt][1] = __float_as_uint(As[(mm + gq + 8) * APITCH + ks + tg]);
                af[mt][2] = __float_as_uint(As[(mm + gq)     * APITCH + ks + tg + 4]);
                af[mt][3] = __float_as_uint(As[(mm + gq + 8) * APITCH + ks + tg + 4]);
            }
#pragma unroll
            for (int mt = 0; mt < 4; mt++)
#pragma unroll
                for (int nt = 0; nt < 4; nt++)
                    mma8(acc[mt][nt][0], acc[mt][nt][1], acc[mt][nt][2], acc[mt][nt][3],
                         af[mt][0], af[mt][1], af[mt][2], af[mt][3],
                         bf[nt][0], bf[nt][1]);
        }
        __syncthreads();
    }

    // ---- epilogue: stage through SMEM for coalesced float4 writes ----
    const float* resb = res ? (res + bz * sRes) : (const float*)0;
    float* Cb = C + bz * sC;

#pragma unroll
    for (int mt = 0; mt < 4; mt++) {
        // store fragments (STS.64, conflict-free: banks 4g+8nt+2tg distinct)
#pragma unroll
        for (int nt = 0; nt < 4; nt++) {
            int col = wn * 32 + nt * 8 + tg * 2;
            int rl  = wm * 16 + gq;
            float2 lo = make_float2(acc[mt][nt][0], acc[mt][nt][1]);
            float2 hi = make_float2(acc[mt][nt][2], acc[mt][nt][3]);
            *(float2*)(stage + rl * SPITCH + col)       = lo;
            *(float2*)(stage + (rl + 8) * SPITCH + col) = hi;
        }
        __syncthreads();

        // 32 rows x 128 cols -> global, fused epilogue
#pragma unroll
        for (int it = 0; it < 4; it++) {
            int lin = tid + it * 256;
            int rl = lin >> 5, q = lin & 31;
            float4 v = *(float4*)(stage + rl * SPITCH + 4 * q);
            int mrow = (rl < 16) ? (mt * 16 + rl) : (64 + mt * 16 + (rl - 16));
            int m = m0 + mrow;
            int n = n0 + 4 * q;
            v.x *= alpha; v.y *= alpha; v.z *= alpha; v.w *= alpha;
            if (bias) {
                float4 bv = *(const float4*)(bias + n);
                v.x += bv.x; v.y += bv.y; v.z += bv.z; v.w += bv.w;
            }
            if (resb) {
                float4 rv = *(const float4*)(resb + (long)m * N + n);
                v.x += rv.x; v.y += rv.y; v.z += rv.z; v.w += rv.w;
            }
            if (RELU) {
                v.x = fmaxf(v.x, 0.0f); v.y = fmaxf(v.y, 0.0f);
                v.z = fmaxf(v.z, 0.0f); v.w = fmaxf(v.w, 0.0f);
            }
            *(float4*)(Cb + (long)m * N + n) = v;
        }
        __syncthreads();
    }
}

// ---------------------------------------------------------------------------
// Masked softmax over the last dim of c[B,G,G] (in place). Matches reference:
// masked -> -30 pre-softmax (contributes to denominator), masked -> 0 post.
// ---------------------------------------------------------------------------
__global__ void __launch_bounds__(256)
softmax_mask_kernel(float* __restrict__ c, const int* __restrict__ mask)
{
    const int q = blockIdx.x;
    const int b = blockIdx.y;
    float* row = c + ((long)b * GG + q) * GG;
    const int* mrow = mask + b * GG;
    const int tid = threadIdx.x;

    float vals[4];
    int   msk[4];
    float mx = -1e30f;
#pragma unroll
    for (int t = 0; t < 4; t++) {
        int idx = tid + t * 256;
        int m = mrow[idx];
        float v = m ? NEGV : row[idx];
        vals[t] = v;
        msk[t]  = m;
        mx = fmaxf(mx, v);
    }

    __shared__ float red[8];
#pragma unroll
    for (int o = 16; o; o >>= 1) mx = fmaxf(mx, __shfl_xor_sync(0xffffffffu, mx, o));
    if ((tid & 31) == 0) red[tid >> 5] = mx;
    __syncthreads();
    mx = fmaxf(fmaxf(fmaxf(red[0], red[1]), fmaxf(red[2], red[3])),
               fmaxf(fmaxf(red[4], red[5]), fmaxf(red[6], red[7])));
    __syncthreads();

    float e[4];
    float s = 0.0f;
#pragma unroll
    for (int t = 0; t < 4; t++) {
        e[t] = __expf(vals[t] - mx);
        s += e[t];
    }
#pragma unroll
    for (int o = 16; o; o >>= 1) s += __shfl_xor_sync(0xffffffffu, s, o);
    if ((tid & 31) == 0) red[tid >> 5] = s;
    __syncthreads();
    float tot = red[0] + red[1] + red[2] + red[3]
              + red[4] + red[5] + red[6] + red[7];
    float inv = 1.0f / tot;

#pragma unroll
    for (int t = 0; t < 4; t++) {
        int idx = tid + t * 256;
        row[idx] = msk[t] ? 0.0f : e[t] * inv;
    }
}

// ---------------------------------------------------------------------------
// mean over G (deterministic, no atomics)
// ---------------------------------------------------------------------------
__global__ void __launch_bounds__(DD)
mean_kernel(const float* __restrict__ h, float* __restrict__ mean)
{
    const int b = blockIdx.x;
    const int d = threadIdx.x;
    const float* p = h + (long)b * GG * DD + d;
    float s = 0.0f;
#pragma unroll 8
    for (int g = 0; g < GG; g++)
        s += p[(long)g * DD];
    mean[b * DD + d] = s * (1.0f / (float)GG);
}

// ---------------------------------------------------------------------------
// Host launcher
// ---------------------------------------------------------------------------
extern "C" void kernel_launch(void* const* d_in, const int* in_sizes, int n_in,
                              void* d_out, int out_size)
{
    (void)in_sizes; (void)n_in; (void)out_size;

    const float* x    = (const float*)d_in[0];
    const int*   mask = (const int*)  d_in[1];
    const float* Wq   = (const float*)d_in[2];
    const float* Wk   = (const float*)d_in[3];
    const float* Wv   = (const float*)d_in[4];
    const float* Wo   = (const float*)d_in[5];
    const float* bo   = (const float*)d_in[6];
    const float* Wf1  = (const float*)d_in[7];
    const float* bf1  = (const float*)d_in[8];
    const float* Wf2  = (const float*)d_in[9];
    const float* bf2  = (const float*)d_in[10];
    float* out = (float*)d_out;

    float *q, *k, *v, *heads, *h, *c, *t;
    cudaGetSymbolAddress((void**)&q,     g_q);
    cudaGetSymbolAddress((void**)&k,     g_k);
    cudaGetSymbolAddress((void**)&v,     g_v);
    cudaGetSymbolAddress((void**)&heads, g_heads);
    cudaGetSymbolAddress((void**)&h,     g_h);
    cudaGetSymbolAddress((void**)&c,     g_c);
    cudaGetSymbolAddress((void**)&t,     g_t);

    const int  BG     = BB * GG;                 // 65536
    const long strQKV = (long)GG * DD;
    const long strC   = (long)GG * GG;
    const dim3 blk(256);

    const dim3 gProj(DD / 128, BG / 128, 1);     // (2, 512)
    const dim3 gScores(GG / 128, GG / 128, BB);  // (8, 8, 64)
    const dim3 gHeads(DD / 128, GG / 128, BB);   // (2, 8, 64)
    const dim3 gFfn1(FF / 128, BG / 128, 1);     // (8, 512)

    const float* hin = x;
    for (int l = 0; l < LL; l++) {
        const float* wq = Wq  + (long)l * DD * DD;
        const float* wk = Wk  + (long)l * DD * DD;
        const float* wv = Wv  + (long)l * DD * DD;
        const float* wo = Wo  + (long)l * DD * DD;
        const float* w1 = Wf1 + (long)l * DD * FF;
        const float* w2 = Wf2 + (long)l * FF * DD;
        const float* b_o = bo  + l * DD;
        const float* b_1 = bf1 + l * FF;
        const float* b_2 = bf2 + l * DD;

        // Q, K, V projections: [BG,D] @ [D,D]  (NN)
        mma_gemm<false, false><<<gProj, blk, SMEM_BYTES>>>(hin, wq, 0, 0, q,
            BG, DD, DD, 0, 0, 0, 0, 1.0f);
        mma_gemm<false, false><<<gProj, blk, SMEM_BYTES>>>(hin, wk, 0, 0, k,
            BG, DD, DD, 0, 0, 0, 0, 1.0f);
        mma_gemm<false, false><<<gProj, blk, SMEM_BYTES>>>(hin, wv, 0, 0, v,
            BG, DD, DD, 0, 0, 0, 0, 1.0f);

        // scores: c[b] = (1/16) * q[b] @ k[b]^T  (NT)
        mma_gemm<true, false><<<gScores, blk, SMEM_BYTES>>>(q, k, 0, 0, c,
            GG, GG, DD, strQKV, strQKV, strC, 0, 0.0625f);

        softmax_mask_kernel<<<dim3(GG, BB), 256>>>(c, mask);

        // heads[b] = a[b] @ v[b]  (NN)
        mma_gemm<false, false><<<gHeads, blk, SMEM_BYTES>>>(c, v, 0, 0, heads,
            GG, DD, GG, strC, strQKV, strQKV, 0, 1.0f);

        // h = hin + heads @ Wo + bo  (NN)
        mma_gemm<false, false><<<gProj, blk, SMEM_BYTES>>>(heads, wo, b_o, hin, h,
            BG, DD, DD, 0, 0, 0, 0, 1.0f);

        // t = relu(h @ Wf1 + bf1)  (NN)
        mma_gemm<false, true><<<gFfn1, blk, SMEM_BYTES>>>(h, w1, b_1, 0, t,
            BG, FF, DD, 0, 0, 0, 0, 1.0f);

        // hout = h + t @ Wf2 + bf2  (NN)
        float* hout = (l == LL - 1) ? out : h;
        mma_gemm<false, false><<<gProj, blk, SMEM_BYTES>>>(t, w2, b_2, h, hout,
            BG, DD, FF, 0, 0, 0, 0, 1.0f);

        hin = h;
    }

    mean_kernel<<<BB, DD>>>(out, out + (long)BB * GG * DD);
}